// round 12
// baseline (speedup 1.0000x reference)
#include <cuda_runtime.h>
#include <cuda_fp16.h>
#include <cstdint>

// Problem constants (fixed for this dataset instance)
#define N_STOCK 2048
#define DIM 128
#define T_MAX 32

// ---------------- scratch (static device memory; no allocations allowed) ----
// mask layout (PERMUTED): word w = step*4 + c  (step = col>>7, c = col&3),
//                         bit  = (col>>2) & 31
__device__ float    g_E2[T_MAX * N_STOCK];                     // exp(f2/scale)
__device__ __half   g_W[(size_t)T_MAX * N_STOCK * DIM];        // [t][n][d] = fp16(E2*v)
__device__ unsigned g_mask[(size_t)T_MAX * N_STOCK * 64];      // permuted bitmask
__device__ float    g_rZ[T_MAX * N_STOCK];                     // 1/Z per (t,row)
__device__ float    g_ACC2[T_MAX][(size_t)N_STOCK * DIM];      // per-t partial sums

// =================== PTX helpers ===================
__device__ __forceinline__ unsigned smem_u32(const void* p) {
    return (unsigned)__cvta_generic_to_shared(p);
}
__device__ __forceinline__ void ldsm_x4(unsigned& r0, unsigned& r1, unsigned& r2, unsigned& r3, unsigned addr) {
    asm volatile("ldmatrix.sync.aligned.m8n8.x4.shared.b16 {%0,%1,%2,%3}, [%4];"
        : "=r"(r0), "=r"(r1), "=r"(r2), "=r"(r3) : "r"(addr));
}
__device__ __forceinline__ void ldsm_x4_t(unsigned& r0, unsigned& r1, unsigned& r2, unsigned& r3, unsigned addr) {
    asm volatile("ldmatrix.sync.aligned.m8n8.x4.trans.shared.b16 {%0,%1,%2,%3}, [%4];"
        : "=r"(r0), "=r"(r1), "=r"(r2), "=r"(r3) : "r"(addr));
}
__device__ __forceinline__ void mma16816(float* c, const unsigned* a, const unsigned* b) {
    asm volatile("mma.sync.aligned.m16n8k16.row.col.f32.f16.f16.f32 "
        "{%0,%1,%2,%3}, {%4,%5,%6,%7}, {%8,%9}, {%0,%1,%2,%3};"
        : "+f"(c[0]), "+f"(c[1]), "+f"(c[2]), "+f"(c[3])
        : "r"(a[0]), "r"(a[1]), "r"(a[2]), "r"(a[3]), "r"(b[0]), "r"(b[1]));
}
#define CP_ASYNC16(dst, src) \
    asm volatile("cp.async.cg.shared.global [%0], [%1], 16;" :: "r"(dst), "l"(src))
#define CP_COMMIT() asm volatile("cp.async.commit_group;" ::: "memory")
#define CP_WAIT(n)  asm volatile("cp.async.wait_group %0;" :: "n"(n) : "memory")

#define AB_STRIDE 136   // 128 + 8 halfs padding (bank-conflict-free ldmatrix)

// C[128x128] += A[128x128] * B[128x128], A/B fp16 in smem (vproj only)
__device__ __forceinline__ void mma_128x128(float acc[4][4][4],
                                            const __half* As, const __half* Bs,
                                            int warp, int lane) {
    const int wm = warp >> 2, wn = warp & 3;
    const int aRow    = lane & 15;
    const int aColSel = (lane >> 4) << 3;
    const int bRow    = (lane & 7) + (lane & 8);
    const int bColSel = (lane >> 4) << 3;
#pragma unroll
    for (int ks = 0; ks < 8; ks++) {
        const int k0 = ks << 4;
        unsigned a[4][4];
#pragma unroll
        for (int ma = 0; ma < 4; ma++) {
            unsigned addr = smem_u32(As + (wm * 64 + ma * 16 + aRow) * AB_STRIDE + k0 + aColSel);
            ldsm_x4(a[ma][0], a[ma][1], a[ma][2], a[ma][3], addr);
        }
        unsigned b[4][2];
#pragma unroll
        for (int nb = 0; nb < 2; nb++) {
            unsigned addr = smem_u32(Bs + (k0 + bRow) * AB_STRIDE + wn * 32 + nb * 16 + bColSel);
            ldsm_x4_t(b[2 * nb][0], b[2 * nb][1], b[2 * nb + 1][0], b[2 * nb + 1][1], addr);
        }
#pragma unroll
        for (int ma = 0; ma < 4; ma++)
#pragma unroll
            for (int na = 0; na < 4; na++)
                mma16816(acc[ma][na], a[ma], b[na]);
    }
}

// ---------------- K1: fused wkeff + E2 ----------------
// grid 64, block 256. Phase 1: block computes wkeff[f] = sum_d Wk[d,f]*f2w[d]
// cooperatively (coalesced over f). Phase 2: 1024 rows/block, warp per row.
__global__ void __launch_bounds__(256)
e2_kernel(const float* __restrict__ input_s, const float* __restrict__ bk,
          const float* __restrict__ Wk, const float* __restrict__ f2w,
          const float* __restrict__ f2b, float rscale) {
    __shared__ __align__(16) float wkeffS[DIM];
    __shared__ __align__(16) float f2wS[DIM];
    int tid = threadIdx.x, warp = tid >> 5, lane = tid & 31;

    if (tid < DIM) f2wS[tid] = f2w[tid];
    __syncthreads();
    if (tid < DIM) {
        float s = 0.f;
#pragma unroll 8
        for (int d = 0; d < DIM; d++) s += Wk[d * DIM + tid] * f2wS[d];
        wkeffS[tid] = s;
    }
    __syncthreads();

    const float f2b0 = f2b[0];
    const float4* wk4 = (const float4*)wkeffS;
    const float4* fw4 = (const float4*)f2wS;
    float4 w = wk4[lane], f = fw4[lane];

    int row0 = blockIdx.x * 1024;
    for (int rr = warp; rr < 1024; rr += 8) {
        int row = row0 + rr;                              // t*N + n
        const float4* in4 = (const float4*)(input_s + (size_t)row * DIM);
        int n = row & (N_STOCK - 1);
        const float4* bk4 = (const float4*)(bk + (size_t)n * DIM);
        float4 a = in4[lane], b = bk4[lane];
        float s = a.x * w.x + a.y * w.y + a.z * w.z + a.w * w.w
                + b.x * f.x + b.y * f.y + b.z * f.z + b.w * f.w;
#pragma unroll
        for (int off = 16; off; off >>= 1) s += __shfl_xor_sync(0xffffffffu, s, off);
        if (lane == 0) g_E2[row] = expf((s + f2b0) * rscale);
    }
}

// ---------------- K2: W[t,n,d] = fp16(E2[t,n] * (input @ Wv^T + bv)[t,n,d]) ----------------
__global__ void __launch_bounds__(256, 2)
vproj_kernel(const float* __restrict__ input_s, const float* __restrict__ Wv,
             const float* __restrict__ bv) {
    extern __shared__ unsigned char smraw[];
    __half* As = (__half*)smraw;                        // 128 x 136 fp16
    __half* Bs = (__half*)(smraw + 128 * AB_STRIDE * 2);
    int tid = threadIdx.x, warp = tid >> 5, lane = tid & 31;
    int wm = warp >> 2, wn = warp & 3;

    for (int idx = tid; idx < DIM * DIM; idx += 256) {
        int d = idx >> 7, f = idx & 127;
        Bs[f * AB_STRIDE + d] = __float2half_rn(Wv[idx]);   // transposed: [f][d]
    }

#pragma unroll
    for (int st = 0; st < 2; st++) {
        size_t row0 = (size_t)blockIdx.x * 256 + (size_t)st * 128;
        int t  = (int)(row0 >> 11);
        int n0 = (int)(row0 & (N_STOCK - 1));

        const float4* src = (const float4*)(input_s + row0 * DIM);
        for (int idx = tid; idx < 128 * 32; idx += 256) {
            int r = idx >> 5, c = idx & 31;
            float4 v = src[r * 32 + c];
            *(__half2*)(As + r * AB_STRIDE + c * 4)     = __floats2half2_rn(v.x, v.y);
            *(__half2*)(As + r * AB_STRIDE + c * 4 + 2) = __floats2half2_rn(v.z, v.w);
        }
        __syncthreads();

        float acc[4][4][4] = {};
        mma_128x128(acc, As, Bs, warp, lane);
        __syncthreads();

#pragma unroll
        for (int ma = 0; ma < 4; ma++)
#pragma unroll
            for (int na = 0; na < 4; na++)
#pragma unroll
                for (int h = 0; h < 2; h++) {
                    int rrow = wm * 64 + ma * 16 + (lane >> 2) + h * 8;
                    int col  = wn * 32 + na * 8 + ((lane & 3) << 1);
                    int n = n0 + rrow;
                    float e2 = g_E2[(size_t)t * N_STOCK + n];
                    float2 bvv = *(const float2*)(bv + (size_t)n * DIM + col);
                    float x = e2 * (acc[ma][na][h * 2]     + bvv.x);
                    float y = e2 * (acc[ma][na][h * 2 + 1] + bvv.y);
                    *(__half2*)(g_W + (row0 + rrow) * DIM + col) = __floats2half2_rn(x, y);
                }
    }
}

// ---------------- K3a: adj -> permuted bitmask + 1/Z ----------------
// grid (N/8, T), block 256 (8 warps = 8 rows/CTA). Per row: 16 coalesced int4
// steps; 4 ballots per step; lane keeps word w=lane (k0) and w=lane+32 (k1).
__global__ void __launch_bounds__(256, 4)
maskz_kernel(const int* __restrict__ adj) {
    __shared__ float E2s[N_STOCK];
    int tid = threadIdx.x, warp = tid >> 5, lane = tid & 31;
    int t = blockIdx.y, row = blockIdx.x * 8 + warp;

    const float4* e4g = (const float4*)(g_E2 + (size_t)t * N_STOCK);
    for (int k = tid; k < N_STOCK / 4; k += 256) ((float4*)E2s)[k] = e4g[k];
    __syncthreads();

    const int4*   arow4 = (const int4*)(adj + ((size_t)t * N_STOCK + row) * N_STOCK);
    const float4* e4    = (const float4*)E2s;
    const int mys = lane >> 2, myc = lane & 3;

    float z = 0.f;
    unsigned k0 = 0, k1 = 0;
#pragma unroll
    for (int s = 0; s < 16; s++) {
        int4   v = arow4[s * 32 + lane];
        float4 e = e4[s * 32 + lane];
        unsigned m0 = __ballot_sync(0xffffffffu, v.x != 0);
        unsigned m1 = __ballot_sync(0xffffffffu, v.y != 0);
        unsigned m2 = __ballot_sync(0xffffffffu, v.z != 0);
        unsigned m3 = __ballot_sync(0xffffffffu, v.w != 0);
        if (v.x) z += e.x;
        if (v.y) z += e.y;
        if (v.z) z += e.z;
        if (v.w) z += e.w;
        unsigned msel = myc == 0 ? m0 : (myc == 1 ? m1 : (myc == 2 ? m2 : m3));
        if ((s & 7) == mys) { if (s < 8) k0 |= msel; else k1 |= msel; }
    }
    // diagonal (adj + I, clamped): force bit at col==row; add E2 if adj diag was 0
    {
        unsigned wd = ((unsigned)(row >> 7) << 2) | (unsigned)(row & 3);
        if ((int)(wd & 31) == lane) {
            unsigned b = 1u << ((row >> 2) & 31);
            unsigned cur = (wd & 32) ? k1 : k0;
            if (!(cur & b)) {
                if (wd & 32) k1 |= b; else k0 |= b;
                z += E2s[row];
            }
        }
    }
#pragma unroll
    for (int off = 16; off; off >>= 1) z += __shfl_xor_sync(0xffffffffu, z, off);
    unsigned* mrow = g_mask + ((size_t)t * N_STOCK + row) * 64;
    mrow[lane]      = k0;
    mrow[lane + 32] = k1;
    if (lane == 0) g_rZ[t * N_STOCK + row] = 1.f / z;
}

// ---------------- K3b: mask-GEMM: ACC2[t] = (mask * rZ) @ W[t] ----------------
// Warp grid 4m x 2n (each warp 32 rows x 64 cols); 3-stage cp.async pipeline,
// one sync/tile; ks-invariant mask words held in registers.
// IDENTICAL to R11 — this round instruments it (now the 4th launch => profiled).
#define B_TILE   (128 * AB_STRIDE * 2)              // 34816
#define SMB_M    (3 * B_TILE)                       // 104448
#define SMB_SIZE (SMB_M + 3 * 2048)                 // 110592

__global__ void __launch_bounds__(256, 2)
gemm_kernel() {
    extern __shared__ unsigned char sm[];
    __half* Bbuf = (__half*)sm;

    int tid = threadIdx.x, warp = tid >> 5, lane = tid & 31;
    int i0 = blockIdx.x * 128, t = blockIdx.y;
    int wm = warp & 3, wn = warp >> 2, g = lane >> 2, t4 = lane & 3;
    const int c0 = (t4 & 1) * 2;    // mask word pair for this thread's k-columns
    const int h  = t4 >> 1;         // bit sub-offset

    const __half* wt = g_W + (size_t)t * N_STOCK * DIM;
    const unsigned* mbase = g_mask + ((size_t)t * N_STOCK + i0) * 64;

    auto issueTile = [&](int jt) {
        int st = jt % 3;
        const char* src = (const char*)(wt + (size_t)(jt << 7) * DIM);
        unsigned dstb = smem_u32(Bbuf) + st * B_TILE;
#pragma unroll
        for (int it = 0; it < 8; it++) {
            int idx = tid + it * 256;
            int r = idx >> 4, c = idx & 15;
            CP_ASYNC16(dstb + r * (AB_STRIDE * 2) + c * 16, src + r * (DIM * 2) + c * 16);
        }
        if (tid < 128) {
            unsigned mdst = smem_u32(sm + SMB_M + st * 2048) + tid * 16;
            CP_ASYNC16(mdst, (const char*)(mbase + (size_t)tid * 64 + (jt << 2)));
        }
        CP_COMMIT();
    };
    issueTile(0);
    issueTile(1);

    float acc[2][8][4] = {};
    const int bRow    = (lane & 7) + (lane & 8);
    const int bColSel = (lane >> 4) << 3;

    for (int jt = 0; jt < 16; jt++) {
        if (jt < 15) { CP_WAIT(1); } else { CP_WAIT(0); }
        __syncthreads();                       // stage jt ready; stage jt-1 fully consumed
        if (jt + 2 < 16) issueTile(jt + 2);    // refill slot freed by tile jt-1
        int st = jt % 3;
        const __half*   Bs = Bbuf + st * (128 * AB_STRIDE);
        const unsigned* Mw = (const unsigned*)(sm + SMB_M + st * 2048);

        // mask words for this tile: ks-invariant -> load once, hold in regs
        uint2 WA[2], WB[2];
#pragma unroll
        for (int ma = 0; ma < 2; ma++) {
            int R0 = wm * 32 + ma * 16 + g;
            WA[ma] = *(const uint2*)(Mw + R0 * 4 + c0);
            WB[ma] = *(const uint2*)(Mw + (R0 + 8) * 4 + c0);
        }

#pragma unroll
        for (int ks = 0; ks < 8; ks++) {
            const int k0 = ks << 4;
            unsigned b[8][2];
#pragma unroll
            for (int nb = 0; nb < 4; nb++) {
                unsigned addr = smem_u32(Bs + (k0 + bRow) * AB_STRIDE + wn * 64 + nb * 16 + bColSel);
                ldsm_x4_t(b[2 * nb][0], b[2 * nb][1], b[2 * nb + 1][0], b[2 * nb + 1][1], addr);
            }
            const int p = ks * 4 + h;
#pragma unroll
            for (int ma = 0; ma < 2; ma++) {
                unsigned ua = WA[ma].x >> p, ub = WA[ma].y >> p;
                unsigned uc = WB[ma].x >> p, ud = WB[ma].y >> p;
                unsigned a[4];
                a[0] = (ua & 1u) * 0x3C00u + (ub & 1u) * 0x3C000000u;
                a[1] = (uc & 1u) * 0x3C00u + (ud & 1u) * 0x3C000000u;
                a[2] = (ua & 4u) * 0x0F00u + (ub & 4u) * 0x0F000000u;
                a[3] = (uc & 4u) * 0x0F00u + (ud & 4u) * 0x0F000000u;
#pragma unroll
                for (int na = 0; na < 8; na++) mma16816(acc[ma][na], a, b[na]);
            }
        }
    }

    // epilogue: rZ scale, private slab store (no atomics)
#pragma unroll
    for (int ma = 0; ma < 2; ma++) {
        int R0 = wm * 32 + ma * 16 + g;
        float rz0 = g_rZ[t * N_STOCK + i0 + R0];
        float rz1 = g_rZ[t * N_STOCK + i0 + R0 + 8];
#pragma unroll
        for (int na = 0; na < 8; na++) {
            int col = wn * 64 + na * 8 + (t4 << 1);
            float* d0 = g_ACC2[t] + (size_t)(i0 + R0) * DIM + col;
            float* d1 = g_ACC2[t] + (size_t)(i0 + R0 + 8) * DIM + col;
            *(float2*)d0 = make_float2(rz0 * acc[ma][na][0], rz0 * acc[ma][na][1]);
            *(float2*)d1 = make_float2(rz1 * acc[ma][na][2], rz1 * acc[ma][na][3]);
        }
    }
}

// ---------------- K4: out = (sum_t ACC2[t]) @ ffn_w^T + T*ffn_b ----------------
__global__ void __launch_bounds__(256)
ffn_kernel(const float* __restrict__ ffn_w, const float* __restrict__ ffn_b,
           float* __restrict__ out, float tmul) {
    __shared__ float Arow[16][DIM];
    int row0 = blockIdx.x * 16;
    for (int idx = threadIdx.x; idx < 16 * DIM; idx += 256) {
        int r = idx >> 7, d = idx & 127;
        float s = 0.f;
#pragma unroll
        for (int g2 = 0; g2 < T_MAX; g2++) s += g_ACC2[g2][(size_t)(row0 + r) * DIM + d];
        Arow[r][d] = s;
    }
    __syncthreads();
    int e  = threadIdx.x & 127;
    int rh = threadIdx.x >> 7;
    float bias = ffn_b[e] * tmul;
    const float* W = ffn_w + (size_t)e * DIM;
    for (int r = rh; r < 16; r += 2) {
        float s = 0.f;
#pragma unroll
        for (int d = 0; d < DIM; d++) s += Arow[r][d] * W[d];
        out[(size_t)(row0 + r) * DIM + e] = s + bias;
    }
}

// ---------------- launch ----------------
extern "C" void kernel_launch(void* const* d_in, const int* in_sizes, int n_in,
                              void* d_out, int out_size) {
    const float* input_s = (const float*)d_in[0];
    const int*   adj     = (const int*)d_in[1];
    // d_in[2] num_stock, d_in[3] Wq, d_in[4] bq unused (f1 cancels in row softmax)
    const float* Wk    = (const float*)d_in[5];
    const float* bk    = (const float*)d_in[6];
    const float* Wv    = (const float*)d_in[7];
    const float* bv    = (const float*)d_in[8];
    // d_in[9] f1_w, d_in[10] f1_b unused
    const float* f2_w  = (const float*)d_in[11];
    const float* f2_b  = (const float*)d_in[12];
    const float* ffn_w = (const float*)d_in[13];
    const float* ffn_b = (const float*)d_in[14];
    float* out = (float*)d_out;

    const int N = in_sizes[4] / DIM;              // 2048
    const int T = in_sizes[0] / (N * DIM);        // 32
    const float rscale = 1.0f / sqrtf((float)DIM);

    cudaFuncSetAttribute(vproj_kernel, cudaFuncAttributeMaxDynamicSharedMemorySize,
                         128 * AB_STRIDE * 2 * 2);
    cudaFuncSetAttribute(gemm_kernel, cudaFuncAttributeMaxDynamicSharedMemorySize, SMB_SIZE);

    // 5 launches: gemm is the 4th => captured by the fixed ncu skip window.
    e2_kernel<<<(T * N) / 1024, 256>>>(input_s, bk, Wk, f2_w, f2_b, rscale);
    vproj_kernel<<<(T * N) / 256, 256, 128 * AB_STRIDE * 2 * 2>>>(input_s, Wv, bv);
    maskz_kernel<<<dim3(N / 8, T), 256>>>(adj);
    gemm_kernel<<<dim3(N / 128, T), 256, SMB_SIZE>>>();
    ffn_kernel<<<N / 16, 256>>>(ffn_w, ffn_b, out, (float)T);
}

// round 13
// speedup vs baseline: 1.3054x; 1.3054x over previous
#include <cuda_runtime.h>
#include <cuda_fp16.h>
#include <cstdint>

// Problem constants (fixed for this dataset instance)
#define N_STOCK 2048
#define DIM 128
#define T_MAX 32

// ---------------- scratch (static device memory; no allocations allowed) ----
// mask layout (PERMUTED): word w = step*4 + c  (step = col>>7, c = col&3),
//                         bit  = (col>>2) & 31
__device__ float    g_E2[T_MAX * N_STOCK];                     // exp(f2/scale)
__device__ __half   g_W[(size_t)T_MAX * N_STOCK * DIM];        // [t][n][d] = fp16(E2*v)
__device__ unsigned g_mask[(size_t)T_MAX * N_STOCK * 64];      // permuted bitmask
__device__ float    g_rZ[T_MAX * N_STOCK];                     // 1/Z per (t,row)
__device__ float    g_ACC2[T_MAX][(size_t)N_STOCK * DIM];      // per-t partial sums

// =================== PTX helpers ===================
__device__ __forceinline__ unsigned smem_u32(const void* p) {
    return (unsigned)__cvta_generic_to_shared(p);
}
__device__ __forceinline__ void ldsm_x4(unsigned& r0, unsigned& r1, unsigned& r2, unsigned& r3, unsigned addr) {
    asm volatile("ldmatrix.sync.aligned.m8n8.x4.shared.b16 {%0,%1,%2,%3}, [%4];"
        : "=r"(r0), "=r"(r1), "=r"(r2), "=r"(r3) : "r"(addr));
}
__device__ __forceinline__ void ldsm_x4_t(unsigned& r0, unsigned& r1, unsigned& r2, unsigned& r3, unsigned addr) {
    asm volatile("ldmatrix.sync.aligned.m8n8.x4.trans.shared.b16 {%0,%1,%2,%3}, [%4];"
        : "=r"(r0), "=r"(r1), "=r"(r2), "=r"(r3) : "r"(addr));
}
__device__ __forceinline__ void mma16816(float* c, const unsigned* a, const unsigned* b) {
    asm volatile("mma.sync.aligned.m16n8k16.row.col.f32.f16.f16.f32 "
        "{%0,%1,%2,%3}, {%4,%5,%6,%7}, {%8,%9}, {%0,%1,%2,%3};"
        : "+f"(c[0]), "+f"(c[1]), "+f"(c[2]), "+f"(c[3])
        : "r"(a[0]), "r"(a[1]), "r"(a[2]), "r"(a[3]), "r"(b[0]), "r"(b[1]));
}
#define CP_ASYNC16(dst, src) \
    asm volatile("cp.async.cg.shared.global [%0], [%1], 16;" :: "r"(dst), "l"(src))
#define CP_COMMIT() asm volatile("cp.async.commit_group;" ::: "memory")
#define CP_WAIT(n)  asm volatile("cp.async.wait_group %0;" :: "n"(n) : "memory")

#define AB_STRIDE 136   // 128 + 8 halfs padding (bank-conflict-free ldmatrix)

// C[128x128] += A[128x128] * B[128x128], A/B fp16 in smem (vproj only)
__device__ __forceinline__ void mma_128x128(float acc[4][4][4],
                                            const __half* As, const __half* Bs,
                                            int warp, int lane) {
    const int wm = warp >> 2, wn = warp & 3;
    const int aRow    = lane & 15;
    const int aColSel = (lane >> 4) << 3;
    const int bRow    = (lane & 7) + (lane & 8);
    const int bColSel = (lane >> 4) << 3;
#pragma unroll
    for (int ks = 0; ks < 8; ks++) {
        const int k0 = ks << 4;
        unsigned a[4][4];
#pragma unroll
        for (int ma = 0; ma < 4; ma++) {
            unsigned addr = smem_u32(As + (wm * 64 + ma * 16 + aRow) * AB_STRIDE + k0 + aColSel);
            ldsm_x4(a[ma][0], a[ma][1], a[ma][2], a[ma][3], addr);
        }
        unsigned b[4][2];
#pragma unroll
        for (int nb = 0; nb < 2; nb++) {
            unsigned addr = smem_u32(Bs + (k0 + bRow) * AB_STRIDE + wn * 32 + nb * 16 + bColSel);
            ldsm_x4_t(b[2 * nb][0], b[2 * nb][1], b[2 * nb + 1][0], b[2 * nb + 1][1], addr);
        }
#pragma unroll
        for (int ma = 0; ma < 4; ma++)
#pragma unroll
            for (int na = 0; na < 4; na++)
                mma16816(acc[ma][na], a[ma], b[na]);
    }
}

// ---------------- K1: fused wkeff + E2 (512 blocks, per-block wkeff) ----------------
// Wk is 64 KB -> L2-resident; 512x redundant wkeff compute is ~free.
__global__ void __launch_bounds__(256)
e2_kernel(const float* __restrict__ input_s, const float* __restrict__ bk,
          const float* __restrict__ Wk, const float* __restrict__ f2w,
          const float* __restrict__ f2b, float rscale) {
    __shared__ __align__(16) float wkeffS[DIM];
    __shared__ __align__(16) float f2wS[DIM];
    int tid = threadIdx.x, warp = tid >> 5, lane = tid & 31;

    if (tid < DIM) f2wS[tid] = f2w[tid];
    __syncthreads();
    if (tid < DIM) {
        float s = 0.f;
#pragma unroll 8
        for (int d = 0; d < DIM; d++) s += Wk[d * DIM + tid] * f2wS[d];
        wkeffS[tid] = s;
    }
    __syncthreads();

    const float f2b0 = f2b[0];
    const float4* wk4 = (const float4*)wkeffS;
    const float4* fw4 = (const float4*)f2wS;
    float4 w = wk4[lane], f = fw4[lane];

    int row0 = blockIdx.x * 128;
    for (int rr = warp; rr < 128; rr += 8) {
        int row = row0 + rr;                              // t*N + n
        const float4* in4 = (const float4*)(input_s + (size_t)row * DIM);
        int n = row & (N_STOCK - 1);
        const float4* bk4 = (const float4*)(bk + (size_t)n * DIM);
        float4 a = in4[lane], b = bk4[lane];
        float s = a.x * w.x + a.y * w.y + a.z * w.z + a.w * w.w
                + b.x * f.x + b.y * f.y + b.z * f.z + b.w * f.w;
#pragma unroll
        for (int off = 16; off; off >>= 1) s += __shfl_xor_sync(0xffffffffu, s, off);
        if (lane == 0) g_E2[row] = expf((s + f2b0) * rscale);
    }
}

// ---------------- K2: W[t,n,d] = fp16(E2[t,n] * (input @ Wv^T + bv)[t,n,d]) ----------------
__global__ void __launch_bounds__(256, 2)
vproj_kernel(const float* __restrict__ input_s, const float* __restrict__ Wv,
             const float* __restrict__ bv) {
    extern __shared__ unsigned char smraw[];
    __half* As = (__half*)smraw;                        // 128 x 136 fp16
    __half* Bs = (__half*)(smraw + 128 * AB_STRIDE * 2);
    int tid = threadIdx.x, warp = tid >> 5, lane = tid & 31;
    int wm = warp >> 2, wn = warp & 3;

    for (int idx = tid; idx < DIM * DIM; idx += 256) {
        int d = idx >> 7, f = idx & 127;
        Bs[f * AB_STRIDE + d] = __float2half_rn(Wv[idx]);   // transposed: [f][d]
    }

#pragma unroll
    for (int st = 0; st < 2; st++) {
        size_t row0 = (size_t)blockIdx.x * 256 + (size_t)st * 128;
        int t  = (int)(row0 >> 11);
        int n0 = (int)(row0 & (N_STOCK - 1));

        const float4* src = (const float4*)(input_s + row0 * DIM);
        for (int idx = tid; idx < 128 * 32; idx += 256) {
            int r = idx >> 5, c = idx & 31;
            float4 v = src[r * 32 + c];
            *(__half2*)(As + r * AB_STRIDE + c * 4)     = __floats2half2_rn(v.x, v.y);
            *(__half2*)(As + r * AB_STRIDE + c * 4 + 2) = __floats2half2_rn(v.z, v.w);
        }
        __syncthreads();

        float acc[4][4][4] = {};
        mma_128x128(acc, As, Bs, warp, lane);
        __syncthreads();

#pragma unroll
        for (int ma = 0; ma < 4; ma++)
#pragma unroll
            for (int na = 0; na < 4; na++)
#pragma unroll
                for (int h = 0; h < 2; h++) {
                    int rrow = wm * 64 + ma * 16 + (lane >> 2) + h * 8;
                    int col  = wn * 32 + na * 8 + ((lane & 3) << 1);
                    int n = n0 + rrow;
                    float e2 = g_E2[(size_t)t * N_STOCK + n];
                    float2 bvv = *(const float2*)(bv + (size_t)n * DIM + col);
                    float x = e2 * (acc[ma][na][h * 2]     + bvv.x);
                    float y = e2 * (acc[ma][na][h * 2 + 1] + bvv.y);
                    *(__half2*)(g_W + (row0 + rrow) * DIM + col) = __floats2half2_rn(x, y);
                }
    }
}

// ---------------- K3a: adj -> permuted bitmask + 1/Z ----------------
// grid (N/8, T), block 256 (8 warps = 8 rows/CTA). 4-step load batches force
// MLP>=4 (ncu showed regs=28 => ptxas held ~no loads in flight; DRAM stuck 66%).
__global__ void __launch_bounds__(256, 4)
maskz_kernel(const int* __restrict__ adj) {
    __shared__ float E2s[N_STOCK];
    int tid = threadIdx.x, warp = tid >> 5, lane = tid & 31;
    int t = blockIdx.y, row = blockIdx.x * 8 + warp;

    const float4* e4g = (const float4*)(g_E2 + (size_t)t * N_STOCK);
    for (int k = tid; k < N_STOCK / 4; k += 256) ((float4*)E2s)[k] = e4g[k];
    __syncthreads();

    const int4*   arow4 = (const int4*)(adj + ((size_t)t * N_STOCK + row) * N_STOCK);
    const float4* e4    = (const float4*)E2s;
    const int mys = lane >> 2, myc = lane & 3;

    float z = 0.f;
    unsigned k0 = 0, k1 = 0;
#pragma unroll
    for (int s4 = 0; s4 < 4; s4++) {
        int4 v[4];
#pragma unroll
        for (int q = 0; q < 4; q++) v[q] = arow4[(s4 * 4 + q) * 32 + lane];
#pragma unroll
        for (int q = 0; q < 4; q++) {
            int s = s4 * 4 + q;
            float4 e = e4[s * 32 + lane];
            unsigned m0 = __ballot_sync(0xffffffffu, v[q].x != 0);
            unsigned m1 = __ballot_sync(0xffffffffu, v[q].y != 0);
            unsigned m2 = __ballot_sync(0xffffffffu, v[q].z != 0);
            unsigned m3 = __ballot_sync(0xffffffffu, v[q].w != 0);
            if (v[q].x) z += e.x;
            if (v[q].y) z += e.y;
            if (v[q].z) z += e.z;
            if (v[q].w) z += e.w;
            unsigned msel = myc == 0 ? m0 : (myc == 1 ? m1 : (myc == 2 ? m2 : m3));
            if ((s & 7) == mys) { if (s < 8) k0 |= msel; else k1 |= msel; }
        }
    }
    // diagonal (adj + I, clamped): force bit at col==row; add E2 if adj diag was 0
    {
        unsigned wd = ((unsigned)(row >> 7) << 2) | (unsigned)(row & 3);
        if ((int)(wd & 31) == lane) {
            unsigned b = 1u << ((row >> 2) & 31);
            unsigned cur = (wd & 32) ? k1 : k0;
            if (!(cur & b)) {
                if (wd & 32) k1 |= b; else k0 |= b;
                z += E2s[row];
            }
        }
    }
#pragma unroll
    for (int off = 16; off; off >>= 1) z += __shfl_xor_sync(0xffffffffu, z, off);
    unsigned* mrow = g_mask + ((size_t)t * N_STOCK + row) * 64;
    mrow[lane]      = k0;
    mrow[lane + 32] = k1;
    if (lane == 0) g_rZ[t * N_STOCK + row] = 1.f / z;
}

// ---------------- K3b: mask-GEMM: ACC2[t] = (mask * rZ) @ W[t] ----------------
// Warp grid 4m x 2n (each warp 32 rows x 64 cols); 3-stage cp.async pipeline,
// one sync/tile; ks-invariant mask words held in registers. IDENTICAL to R12
// (measured 129.3us, tensor=49.6%) — 4th launch, stays profiled.
#define B_TILE   (128 * AB_STRIDE * 2)              // 34816
#define SMB_M    (3 * B_TILE)                       // 104448
#define SMB_SIZE (SMB_M + 3 * 2048)                 // 110592

__global__ void __launch_bounds__(256, 2)
gemm_kernel() {
    extern __shared__ unsigned char sm[];
    __half* Bbuf = (__half*)sm;

    int tid = threadIdx.x, warp = tid >> 5, lane = tid & 31;
    int i0 = blockIdx.x * 128, t = blockIdx.y;
    int wm = warp & 3, wn = warp >> 2, g = lane >> 2, t4 = lane & 3;
    const int c0 = (t4 & 1) * 2;    // mask word pair for this thread's k-columns
    const int h  = t4 >> 1;         // bit sub-offset

    const __half* wt = g_W + (size_t)t * N_STOCK * DIM;
    const unsigned* mbase = g_mask + ((size_t)t * N_STOCK + i0) * 64;

    auto issueTile = [&](int jt) {
        int st = jt % 3;
        const char* src = (const char*)(wt + (size_t)(jt << 7) * DIM);
        unsigned dstb = smem_u32(Bbuf) + st * B_TILE;
#pragma unroll
        for (int it = 0; it < 8; it++) {
            int idx = tid + it * 256;
            int r = idx >> 4, c = idx & 15;
            CP_ASYNC16(dstb + r * (AB_STRIDE * 2) + c * 16, src + r * (DIM * 2) + c * 16);
        }
        if (tid < 128) {
            unsigned mdst = smem_u32(sm + SMB_M + st * 2048) + tid * 16;
            CP_ASYNC16(mdst, (const char*)(mbase + (size_t)tid * 64 + (jt << 2)));
        }
        CP_COMMIT();
    };
    issueTile(0);
    issueTile(1);

    float acc[2][8][4] = {};
    const int bRow    = (lane & 7) + (lane & 8);
    const int bColSel = (lane >> 4) << 3;

    for (int jt = 0; jt < 16; jt++) {
        if (jt < 15) { CP_WAIT(1); } else { CP_WAIT(0); }
        __syncthreads();                       // stage jt ready; stage jt-1 fully consumed
        if (jt + 2 < 16) issueTile(jt + 2);    // refill slot freed by tile jt-1
        int st = jt % 3;
        const __half*   Bs = Bbuf + st * (128 * AB_STRIDE);
        const unsigned* Mw = (const unsigned*)(sm + SMB_M + st * 2048);

        // mask words for this tile: ks-invariant -> load once, hold in regs
        uint2 WA[2], WB[2];
#pragma unroll
        for (int ma = 0; ma < 2; ma++) {
            int R0 = wm * 32 + ma * 16 + g;
            WA[ma] = *(const uint2*)(Mw + R0 * 4 + c0);
            WB[ma] = *(const uint2*)(Mw + (R0 + 8) * 4 + c0);
        }

#pragma unroll
        for (int ks = 0; ks < 8; ks++) {
            const int k0 = ks << 4;
            unsigned b[8][2];
#pragma unroll
            for (int nb = 0; nb < 4; nb++) {
                unsigned addr = smem_u32(Bs + (k0 + bRow) * AB_STRIDE + wn * 64 + nb * 16 + bColSel);
                ldsm_x4_t(b[2 * nb][0], b[2 * nb][1], b[2 * nb + 1][0], b[2 * nb + 1][1], addr);
            }
            const int p = ks * 4 + h;
#pragma unroll
            for (int ma = 0; ma < 2; ma++) {
                unsigned ua = WA[ma].x >> p, ub = WA[ma].y >> p;
                unsigned uc = WB[ma].x >> p, ud = WB[ma].y >> p;
                unsigned a[4];
                a[0] = (ua & 1u) * 0x3C00u + (ub & 1u) * 0x3C000000u;
                a[1] = (uc & 1u) * 0x3C00u + (ud & 1u) * 0x3C000000u;
                a[2] = (ua & 4u) * 0x0F00u + (ub & 4u) * 0x0F000000u;
                a[3] = (uc & 4u) * 0x0F00u + (ud & 4u) * 0x0F000000u;
#pragma unroll
                for (int na = 0; na < 8; na++) mma16816(acc[ma][na], a, b[na]);
            }
        }
    }

    // epilogue: rZ scale, private slab store (no atomics)
#pragma unroll
    for (int ma = 0; ma < 2; ma++) {
        int R0 = wm * 32 + ma * 16 + g;
        float rz0 = g_rZ[t * N_STOCK + i0 + R0];
        float rz1 = g_rZ[t * N_STOCK + i0 + R0 + 8];
#pragma unroll
        for (int na = 0; na < 8; na++) {
            int col = wn * 64 + na * 8 + (t4 << 1);
            float* d0 = g_ACC2[t] + (size_t)(i0 + R0) * DIM + col;
            float* d1 = g_ACC2[t] + (size_t)(i0 + R0 + 8) * DIM + col;
            *(float2*)d0 = make_float2(rz0 * acc[ma][na][0], rz0 * acc[ma][na][1]);
            *(float2*)d1 = make_float2(rz1 * acc[ma][na][2], rz1 * acc[ma][na][3]);
        }
    }
}

// ---------------- K4: out = (sum_t ACC2[t]) @ ffn_w^T + T*ffn_b ----------------
__global__ void __launch_bounds__(256)
ffn_kernel(const float* __restrict__ ffn_w, const float* __restrict__ ffn_b,
           float* __restrict__ out, float tmul) {
    __shared__ float Arow[16][DIM];
    int row0 = blockIdx.x * 16;
    for (int idx = threadIdx.x; idx < 16 * DIM; idx += 256) {
        int r = idx >> 7, d = idx & 127;
        float s = 0.f;
#pragma unroll
        for (int g2 = 0; g2 < T_MAX; g2++) s += g_ACC2[g2][(size_t)(row0 + r) * DIM + d];
        Arow[r][d] = s;
    }
    __syncthreads();
    int e  = threadIdx.x & 127;
    int rh = threadIdx.x >> 7;
    float bias = ffn_b[e] * tmul;
    const float* W = ffn_w + (size_t)e * DIM;
    for (int r = rh; r < 16; r += 2) {
        float s = 0.f;
#pragma unroll
        for (int d = 0; d < DIM; d++) s += Arow[r][d] * W[d];
        out[(size_t)(row0 + r) * DIM + e] = s + bias;
    }
}

// ---------------- launch ----------------
extern "C" void kernel_launch(void* const* d_in, const int* in_sizes, int n_in,
                              void* d_out, int out_size) {
    const float* input_s = (const float*)d_in[0];
    const int*   adj     = (const int*)d_in[1];
    // d_in[2] num_stock, d_in[3] Wq, d_in[4] bq unused (f1 cancels in row softmax)
    const float* Wk    = (const float*)d_in[5];
    const float* bk    = (const float*)d_in[6];
    const float* Wv    = (const float*)d_in[7];
    const float* bv    = (const float*)d_in[8];
    // d_in[9] f1_w, d_in[10] f1_b unused
    const float* f2_w  = (const float*)d_in[11];
    const float* f2_b  = (const float*)d_in[12];
    const float* ffn_w = (const float*)d_in[13];
    const float* ffn_b = (const float*)d_in[14];
    float* out = (float*)d_out;

    const int N = in_sizes[4] / DIM;              // 2048
    const int T = in_sizes[0] / (N * DIM);        // 32
    const float rscale = 1.0f / sqrtf((float)DIM);

    cudaFuncSetAttribute(vproj_kernel, cudaFuncAttributeMaxDynamicSharedMemorySize,
                         128 * AB_STRIDE * 2 * 2);
    cudaFuncSetAttribute(gemm_kernel, cudaFuncAttributeMaxDynamicSharedMemorySize, SMB_SIZE);

    // 5 launches: gemm is the 4th => captured by the fixed ncu skip window.
    e2_kernel<<<(T * N) / 128, 256>>>(input_s, bk, Wk, f2_w, f2_b, rscale);
    vproj_kernel<<<(T * N) / 256, 256, 128 * AB_STRIDE * 2 * 2>>>(input_s, Wv, bv);
    maskz_kernel<<<dim3(N / 8, T), 256>>>(adj);
    gemm_kernel<<<dim3(N / 128, T), 256, SMB_SIZE>>>();
    ffn_kernel<<<N / 16, 256>>>(ffn_w, ffn_b, out, (float)T);
}